// round 17
// baseline (speedup 1.0000x reference)
#include <cuda_runtime.h>
#include <cuda_bf16.h>

// Sparsemax rows of 2048 fp32 — persistent CTA-per-row with register prefetch
// (the proven structure), occupancy squeezed to 7 CTAs/SM via a 36-register
// budget (__launch_bounds__(256, 7)). Everything else identical to the best:
//  - THETA = 2.5 static threshold: ~13 candidates/row; tau >= THETA
//    self-certifies exactness via KKT (all discarded <= THETA <= tau),
//    fail-closed to the full-block fallback otherwise.
//  - max-tree prefiltered shared-atomic gather; warp-0 Michelot with a
//    single-register fast path for n <= 32 (~99.9% of rows).
//  - register prefetch of the next row before the barriers; streaming
//    __ldcs/__stcs; coalesced float4 stores.

#define ROWLEN  2048
#define THREADS 256
#define VPT     (ROWLEN / THREADS)   // 8
#define NWARP   (THREADS / 32)       // 8
#define F4PROW  (ROWLEN / 4)         // 512
#define CAP     64
#define THETA   2.5f
#define NEG_INF (-3.0e38f)
#define FULLM   0xffffffffu
#define OCC     7
#define GRID_CTAS (148 * OCC)

__global__ __launch_bounds__(THREADS, OCC)
void sparsemax_kernel(const float* __restrict__ z, float* __restrict__ out, int rows) {
    const float4* __restrict__ z4   = reinterpret_cast<const float4*>(z);
    float4* __restrict__       out4 = reinterpret_cast<float4*>(out);
    const int tid  = threadIdx.x;
    const int lane = tid & 31;
    const int wid  = tid >> 5;
    const long long stride = gridDim.x;

    __shared__ float s_cand[CAP];
    __shared__ int   s_n;
    __shared__ float s_tau;
    __shared__ int   s_ok;
    __shared__ float s_red[NWARP];
    __shared__ float s_cnt[NWARP];

    long long r = blockIdx.x;
    if (r >= rows) return;

    if (tid == 0) s_n = 0;

    // prime the pipeline: loads for the first row
    float4 a = __ldcs(&z4[r * F4PROW + tid]);
    float4 b = __ldcs(&z4[r * F4PROW + THREADS + tid]);
    __syncthreads();   // s_n init visible

    #pragma unroll 1
    while (true) {
        const long long rn = r + stride;
        float v[VPT] = {a.x, a.y, a.z, a.w, b.x, b.y, b.z, b.w};

        // ---- gather candidates > THETA (max-tree prefilter, rare atomics) ----
        float m = fmaxf(fmaxf(fmaxf(v[0], v[1]), fmaxf(v[2], v[3])),
                        fmaxf(fmaxf(v[4], v[5]), fmaxf(v[6], v[7])));
        if (m > THETA) {
            #pragma unroll
            for (int i = 0; i < VPT; i++) {
                if (v[i] > THETA) {
                    int idx = atomicAdd(&s_n, 1);
                    if (idx < CAP) s_cand[idx] = v[i];
                }
            }
        }

        // ---- prefetch next row BEFORE barriers/solve (hides DRAM latency) ----
        if (rn < rows) {
            a = __ldcs(&z4[rn * F4PROW + tid]);
            b = __ldcs(&z4[rn * F4PROW + THREADS + tid]);
        }
        __syncthreads();   // gather complete

        // ---- warp 0: Michelot on candidate set; certify tau >= THETA ----
        if (wid == 0) {
            const int n = s_n;
            float tau;
            if (n <= 32) {
                // fast path: one candidate register per lane (~99.9% of rows)
                float c0 = (lane < n) ? s_cand[lane] : NEG_INF;
                float s0 = (c0 > NEG_INF ? c0 : 0.0f);
                #pragma unroll
                for (int o = 16; o > 0; o >>= 1) s0 += __shfl_xor_sync(FULLM, s0, o);
                tau = (s0 - 1.0f) / (float)(n > 0 ? n : 1);
                int prev = -1;
                #pragma unroll 1
                for (int it = 0; it < 32; it++) {
                    float s = 0.0f, cnt = 0.0f;
                    bool a0 = c0 > tau;
                    s   += a0 ? c0 : 0.0f;
                    cnt += a0 ? 1.0f : 0.0f;
                    #pragma unroll
                    for (int o = 16; o > 0; o >>= 1) {
                        s   += __shfl_xor_sync(FULLM, s, o);
                        cnt += __shfl_xor_sync(FULLM, cnt, o);
                    }
                    if (cnt == 0.0f) break;
                    tau = (s - 1.0f) / cnt;
                    int k = (int)cnt;
                    if (k == prev) break;
                    prev = k;
                }
            } else {
                // two candidate registers per lane (n in (32, 64])
                float c0 = (lane < n)      ? s_cand[lane]      : NEG_INF;
                float c1 = (lane + 32 < n) ? s_cand[lane + 32] : NEG_INF;
                float s0 = (c0 > NEG_INF ? c0 : 0.0f) + (c1 > NEG_INF ? c1 : 0.0f);
                #pragma unroll
                for (int o = 16; o > 0; o >>= 1) s0 += __shfl_xor_sync(FULLM, s0, o);
                tau = (s0 - 1.0f) / (float)(n <= CAP ? n : CAP);
                int prev = -1;
                #pragma unroll 1
                for (int it = 0; it < 32; it++) {
                    float s = 0.0f, cnt = 0.0f;
                    bool a0 = c0 > tau, a1 = c1 > tau;
                    s += a0 ? c0 : 0.0f;  cnt += a0 ? 1.0f : 0.0f;
                    s += a1 ? c1 : 0.0f;  cnt += a1 ? 1.0f : 0.0f;
                    #pragma unroll
                    for (int o = 16; o > 0; o >>= 1) {
                        s   += __shfl_xor_sync(FULLM, s, o);
                        cnt += __shfl_xor_sync(FULLM, cnt, o);
                    }
                    if (cnt == 0.0f) break;
                    tau = (s - 1.0f) / cnt;
                    int k = (int)cnt;
                    if (k == prev) break;
                    prev = k;
                }
            }
            if (lane == 0) {
                s_tau = tau;
                s_ok  = (n > 0 && n <= CAP && tau >= THETA) ? 1 : 0;
                s_n   = 0;   // next gather begins only after the next barrier
            }
        }
        __syncthreads();   // s_tau/s_ok visible, s_n reset

        if (s_ok) {
            // ---- fast path: coalesced streaming projection store ----
            const float tau = s_tau;
            float4 o0, o1;
            o0.x = fmaxf(v[0] - tau, 0.0f);
            o0.y = fmaxf(v[1] - tau, 0.0f);
            o0.z = fmaxf(v[2] - tau, 0.0f);
            o0.w = fmaxf(v[3] - tau, 0.0f);
            o1.x = fmaxf(v[4] - tau, 0.0f);
            o1.y = fmaxf(v[5] - tau, 0.0f);
            o1.z = fmaxf(v[6] - tau, 0.0f);
            o1.w = fmaxf(v[7] - tau, 0.0f);
            __stcs(&out4[r * F4PROW + tid],           o0);
            __stcs(&out4[r * F4PROW + THREADS + tid], o1);
        } else {
            // ---- fallback: full-block Michelot over register-resident row ----
            float tau;
            {
                float s = 0.0f;
                #pragma unroll
                for (int i = 0; i < VPT; i++) s += v[i];
                #pragma unroll
                for (int o = 16; o > 0; o >>= 1) s += __shfl_xor_sync(FULLM, s, o);
                if (lane == 0) s_red[wid] = s;
                __syncthreads();
                if (tid == 0) {
                    float tot = 0.0f;
                    #pragma unroll
                    for (int w = 0; w < NWARP; w++) tot += s_red[w];
                    s_tau = (tot - 1.0f) * (1.0f / (float)ROWLEN);
                }
                __syncthreads();
                tau = s_tau;
            }
            int k_prev = ROWLEN;
            #pragma unroll 1
            for (int it = 0; it < 64; it++) {
                float s = 0.0f, cf = 0.0f;
                #pragma unroll
                for (int i = 0; i < VPT; i++) {
                    bool act = v[i] > tau;
                    s  += act ? v[i] : 0.0f;
                    cf += act ? 1.0f : 0.0f;
                }
                #pragma unroll
                for (int o = 16; o > 0; o >>= 1) {
                    s  += __shfl_xor_sync(FULLM, s, o);
                    cf += __shfl_xor_sync(FULLM, cf, o);
                }
                if (lane == 0) { s_red[wid] = s; s_cnt[wid] = cf; }
                __syncthreads();
                if (tid == 0) {
                    float ts = 0.0f, tc = 0.0f;
                    #pragma unroll
                    for (int w = 0; w < NWARP; w++) { ts += s_red[w]; tc += s_cnt[w]; }
                    s_tau = (ts - 1.0f) / tc;
                    s_cnt[0] = tc;
                }
                __syncthreads();
                tau = s_tau;
                int k = (int)s_cnt[0];
                __syncthreads();
                if (k == k_prev) break;
                k_prev = k;
            }
            float4 o0, o1;
            o0.x = fmaxf(v[0] - tau, 0.0f);
            o0.y = fmaxf(v[1] - tau, 0.0f);
            o0.z = fmaxf(v[2] - tau, 0.0f);
            o0.w = fmaxf(v[3] - tau, 0.0f);
            o1.x = fmaxf(v[4] - tau, 0.0f);
            o1.y = fmaxf(v[5] - tau, 0.0f);
            o1.z = fmaxf(v[6] - tau, 0.0f);
            o1.w = fmaxf(v[7] - tau, 0.0f);
            out4[r * F4PROW + tid]           = o0;
            out4[r * F4PROW + THREADS + tid] = o1;
        }

        if (rn >= rows) break;
        r = rn;
    }
}

extern "C" void kernel_launch(void* const* d_in, const int* in_sizes, int n_in,
                              void* d_out, int out_size) {
    const float* z = (const float*)d_in[0];
    float* out = (float*)d_out;
    int rows = in_sizes[0] / ROWLEN;
    int grid = GRID_CTAS < rows ? GRID_CTAS : rows;
    sparsemax_kernel<<<grid, THREADS>>>(z, out, rows);
}